// round 13
// baseline (speedup 1.0000x reference)
#include <cuda_runtime.h>
#include <cuda_fp16.h>

// ---------------------------------------------------------------------------
// MultiHeadSelfAttention, fp16 mma.sync (m16n8k16, fp32 accum) + cp.async.
// f16x2 words pack the k-pair (k, k+8) of a 16-k slab consistently across
// A and B operands (permutation-invariant dot products).
//   prep      : x -> f16x2 pair-interleaved; Wqkv/Wout -> A-fragment order.
//   qkv_gemm  : BK=32, 4-stage one-barrier pipeline. Q scaled by
//               0.125*log2(e) (softmax runs in exp2 domain).
//   flash_attn: two independent 4-warp groups, 64-KEY tiles, private 2-stage
//               rings + named barriers, exp2 softmax in registers.
//   out_gemm  : BK=32, 4-stage pipeline on f16x2 pair-interleaved O.
// ---------------------------------------------------------------------------

#define BATCH 4
#define CDIM  512
#define SEQ   2304
#define NH    8
#define HD    64
#define MQKV  1536
#define SCRH  (BATCH * CDIM * SEQ / 2)

#define QSCALE (0.125f * 1.4426950408889634f)   // d^-1/2 * log2(e)

__device__ __align__(16) unsigned g_Q[SCRH];
__device__ __align__(16) unsigned g_K[SCRH];   // ((bh*2+dpp)*2304+t)*16 + p
__device__ __align__(16) unsigned g_V[SCRH];   // ((bh*72+tblk)*64+d)*16 + p
__device__ __align__(16) unsigned g_O[SCRH];   // ((b*32+ks)*2304+s)*8 + pw
__device__ __align__(16) unsigned g_Xt[SCRH];
__device__ __align__(16) unsigned g_Wq[MQKV * CDIM / 2];
__device__ __align__(16) unsigned g_Wo[CDIM * CDIM / 2];

__device__ __forceinline__ unsigned h2(float lo, float hi) {
    __half2 t = __floats2half2_rn(lo, hi);
    return *(unsigned*)&t;
}

__device__ __forceinline__ void mma_f16(float* c, const unsigned* a,
                                        unsigned b0, unsigned b1) {
    asm volatile(
        "mma.sync.aligned.m16n8k16.row.col.f32.f16.f16.f32 "
        "{%0,%1,%2,%3}, {%4,%5,%6,%7}, {%8,%9}, {%0,%1,%2,%3};"
        : "+f"(c[0]), "+f"(c[1]), "+f"(c[2]), "+f"(c[3])
        : "r"(a[0]), "r"(a[1]), "r"(a[2]), "r"(a[3]), "r"(b0), "r"(b1));
}

__device__ __forceinline__ void cp16(unsigned* dst, const unsigned* src) {
    unsigned da = (unsigned)__cvta_generic_to_shared(dst);
    asm volatile("cp.async.cg.shared.global [%0], [%1], 16;"
                 :: "r"(da), "l"(src));
}
__device__ __forceinline__ void cpcommit() {
    asm volatile("cp.async.commit_group;");
}
template <int N> __device__ __forceinline__ void cpwait() {
    asm volatile("cp.async.wait_group %0;" :: "n"(N));
}

// ---------------------------------------------------------------------------
__global__ void prep(const float* __restrict__ x,
                     const float* __restrict__ Wqkv,
                     const float* __restrict__ Wout)
{
    const int stride = gridDim.x * blockDim.x;
    const int i0 = blockIdx.x * blockDim.x + threadIdx.x;
    for (int o = i0; o < SCRH; o += stride) {
        const int pos = o & 7;
        const int idx = o >> 3;
        const int s = idx % 2304;
        const int slab = idx / 2304;
        const int w = (pos >> 1) + (pos & 1) * 4;
        const int b = slab >> 5;
        const int k = (slab & 31) * 16 + w;
        g_Xt[o] = h2(x[((size_t)(b * 512 + k)) * 2304 + s],
                     x[((size_t)(b * 512 + k + 8)) * 2304 + s]);
    }
    for (int o = i0; o < MQKV * CDIM / 2; o += stride) {
        const int j = o & 3, lane = (o >> 2) & 31, g = (o >> 7) & 7;
        const int ks = (o >> 10) & 31, mb = o >> 15;
        const int m = mb * 128 + g * 16 + (j & 1) * 8 + (lane >> 2);
        const int klo = ks * 16 + (lane & 3) + (j >> 1) * 4;
        g_Wq[o] = h2(Wqkv[m * CDIM + klo], Wqkv[m * CDIM + klo + 8]);
    }
    for (int o = i0; o < CDIM * CDIM / 2; o += stride) {
        const int j = o & 3, lane = (o >> 2) & 31, g = (o >> 7) & 7;
        const int ks = (o >> 10) & 31, mb = o >> 15;
        const int m = mb * 128 + g * 16 + (j & 1) * 8 + (lane >> 2);
        const int klo = ks * 16 + (lane & 3) + (j >> 1) * 4;
        g_Wo[o] = h2(Wout[m * CDIM + klo], Wout[m * CDIM + klo + 8]);
    }
}

// ---------------------------------------------------------------------------
// Projection mainloop (unchanged from R12): BK=32, 4-stage pipeline.
// ---------------------------------------------------------------------------
#define PRJ_STG  4096
#define PRJ_SMEM (4 * PRJ_STG * 4)

#define PRJ_ISSUE(s_, ks0_) {                                                  \
    unsigned* st_ = smp + (s_) * PRJ_STG;                                      \
    const unsigned* ws_ = Wg + (ks0_) * 1024;                                  \
    cp16(st_ + tid * 8,     ws_ + tid * 8);                                    \
    cp16(st_ + tid * 8 + 4, ws_ + tid * 8 + 4);                                \
    _Pragma("unroll") for (int j_ = 0; j_ < 2; j_++) {                         \
        const int c_ = tid * 2 + j_;                                           \
        const int sl_ = c_ >> 8, n_ = (c_ & 255) >> 1, h_ = (c_ & 1) * 4;      \
        cp16(st_ + 2048 + sl_ * 1024 + n_ * 8 + h_,                            \
             Xg + ((size_t)(ks0_) + sl_) * 18432 + n_ * 8 + h_);               \
    }                                                                          \
    cpcommit(); }

#define PRJ_MAINLOOP()                                                         \
    float acc[4][4][4];                                                        \
    _Pragma("unroll") for (int i = 0; i < 4; i++)                              \
    _Pragma("unroll") for (int j = 0; j < 4; j++)                              \
    _Pragma("unroll") for (int k = 0; k < 4; k++) acc[i][j][k] = 0.0f;         \
    PRJ_ISSUE(0, 0)                                                            \
    PRJ_ISSUE(1, 2)                                                            \
    PRJ_ISSUE(2, 4)                                                            \
    for (int it = 0; it < 16; it++) {                                          \
        if (it == 15) cpwait<0>();                                             \
        else if (it == 14) cpwait<1>();                                        \
        else cpwait<2>();                                                      \
        __syncthreads();                                                       \
        if (it < 13) PRJ_ISSUE((it + 3) & 3, (it + 3) * 2)                     \
        unsigned* Ws = smp + (it & 3) * PRJ_STG;                               \
        unsigned* Xs = Ws + 2048;                                              \
        _Pragma("unroll")                                                      \
        for (int ss = 0; ss < 2; ss++) {                                       \
            uint4 afr[4];                                                      \
            _Pragma("unroll") for (int tm = 0; tm < 4; tm++)                   \
                afr[tm] = *(const uint4*)&Ws[ss * 1024 +                       \
                                             ((wm >> 4) + tm) * 128 + lane * 4];\
            uint2 bfr[4];                                                      \
            _Pragma("unroll") for (int tn = 0; tn < 4; tn++)                   \
                bfr[tn] = *(const uint2*)&Xs[ss * 1024 +                       \
                                             (wn + tn * 8 + r) * 8 + q * 2];   \
            _Pragma("unroll") for (int tm = 0; tm < 4; tm++)                   \
            _Pragma("unroll") for (int tn = 0; tn < 4; tn++)                   \
                mma_f16(acc[tm][tn], (const unsigned*)&afr[tm],                \
                        bfr[tn].x, bfr[tn].y);                                 \
        }                                                                      \
    }

// ---------------------------------------------------------------------------
__global__ __launch_bounds__(256, 2) void qkv_gemm(const float* __restrict__ bias)
{
    extern __shared__ unsigned smp[];
    const int tid = threadIdx.x;
    const int b = blockIdx.z, m0 = blockIdx.y * 128, n0 = blockIdx.x * 128;
    const int lane = tid & 31, warp = tid >> 5;
    const int q = lane & 3, r = lane >> 2;
    const int wm = (warp >> 2) * 64, wn = (warp & 3) * 32;
    const unsigned* Wg = g_Wq + (size_t)(m0 >> 7) * 32768;
    const unsigned* Xg = g_Xt + (size_t)b * 589824 + (size_t)n0 * 8;

    PRJ_MAINLOOP()

    const int which = m0 >> 9;
    if (which == 0) {
#pragma unroll
        for (int tm = 0; tm < 4; tm++) {
            const int mA = m0 + wm + tm * 16 + r;
            const int loc = mA & 511, h = loc >> 6, dA = loc & 63;
            const int bh = b * NH + h, dp = dA >> 4;
            const float bvA = bias[mA], bvB = bias[mA + 8];
            unsigned* row = g_Q + (size_t)(bh * 32 + dp * 8 + r) * 2304;
#pragma unroll
            for (int tn = 0; tn < 4; tn++) {
                const int n = n0 + wn + tn * 8 + 2 * q;
                uint2 v;
                v.x = h2((acc[tm][tn][0] + bvA) * QSCALE,
                         (acc[tm][tn][2] + bvB) * QSCALE);
                v.y = h2((acc[tm][tn][1] + bvA) * QSCALE,
                         (acc[tm][tn][3] + bvB) * QSCALE);
                *(uint2*)(row + n) = v;
            }
        }
    } else if (which == 1) {
#pragma unroll
        for (int tm = 0; tm < 4; tm++) {
            const int mA = m0 + wm + tm * 16 + r;
            const int loc = mA & 511, h = loc >> 6, dA = loc & 63;
            const int bh = b * NH + h, dp = dA >> 4;
            const int p0 = (r & 3) * 4 + (r >> 2) + 2 * (dp & 1);
            const float bvA = bias[mA], bvB = bias[mA + 8];
            const size_t base = (size_t)(bh * 2 + (dp >> 1)) * 36864 + p0;
#pragma unroll
            for (int tn = 0; tn < 4; tn++) {
                const int n = n0 + wn + tn * 8 + 2 * q;
                g_K[base + (size_t)n * 16]       = h2(acc[tm][tn][0] + bvA,
                                                      acc[tm][tn][2] + bvB);
                g_K[base + (size_t)(n + 1) * 16] = h2(acc[tm][tn][1] + bvA,
                                                      acc[tm][tn][3] + bvB);
            }
        }
    } else {
#pragma unroll
        for (int tm = 0; tm < 4; tm++) {
            const int mA = m0 + wm + tm * 16 + r;
            const int loc = mA & 511, h = loc >> 6, dA = loc & 63;
            const int bh = b * NH + h;
            const float bvA = bias[mA], bvB = bias[mA + 8];
#pragma unroll
            for (int tnp = 0; tnp < 2; tnp++) {
                const int tn = tnp * 2;
                const int t0 = n0 + wn + tn * 8 + 2 * q;
                const int sub = (t0 >> 4) & 1;
                const int p0 = ((2 * q) & 3) * 4 + ((2 * q) >> 2) + 2 * sub;
                const int p1 = ((2 * q + 1) & 3) * 4 + ((2 * q + 1) >> 2) + 2 * sub;
                const size_t blk = (size_t)(bh * 72 + (t0 >> 5)) * 1024;
                g_V[blk + dA * 16 + p0] = h2(acc[tm][tn][0] + bvA,
                                             acc[tm][tn + 1][0] + bvA);
                g_V[blk + dA * 16 + p1] = h2(acc[tm][tn][1] + bvA,
                                             acc[tm][tn + 1][1] + bvA);
                g_V[blk + (dA + 8) * 16 + p0] = h2(acc[tm][tn][2] + bvB,
                                                   acc[tm][tn + 1][2] + bvB);
                g_V[blk + (dA + 8) * 16 + p1] = h2(acc[tm][tn][3] + bvB,
                                                   acc[tm][tn + 1][3] + bvB);
            }
        }
    }
}

// ---------------------------------------------------------------------------
__global__ __launch_bounds__(256, 2) void out_gemm(const float* __restrict__ bias,
                                                   float* __restrict__ Y)
{
    extern __shared__ unsigned smp[];
    const int tid = threadIdx.x;
    const int b = blockIdx.z, m0 = blockIdx.y * 128, n0 = blockIdx.x * 128;
    const int lane = tid & 31, warp = tid >> 5;
    const int q = lane & 3, r = lane >> 2;
    const int wm = (warp >> 2) * 64, wn = (warp & 3) * 32;
    const unsigned* Wg = g_Wo + (size_t)(m0 >> 7) * 32768;
    const unsigned* Xg = g_O + (size_t)b * 589824 + (size_t)n0 * 8;

    PRJ_MAINLOOP()

#pragma unroll
    for (int tm = 0; tm < 4; tm++) {
        const int mA = m0 + wm + tm * 16 + r;
        const float bvA = bias[mA], bvB = bias[mA + 8];
        float* rowA = Y + ((size_t)b * CDIM + mA) * SEQ;
        float* rowB = Y + ((size_t)b * CDIM + mA + 8) * SEQ;
#pragma unroll
        for (int tn = 0; tn < 4; tn++) {
            const int n = n0 + wn + tn * 8 + 2 * q;
            *(float2*)(rowA + n) = make_float2(acc[tm][tn][0] + bvA,
                                               acc[tm][tn][1] + bvA);
            *(float2*)(rowB + n) = make_float2(acc[tm][tn][2] + bvB,
                                               acc[tm][tn][3] + bvB);
        }
    }
}

// ---------------------------------------------------------------------------
// flash_attn: grid (18, 32), 256 thr, 2 CTAs/SM. Two independent 4-warp
// groups, 64-KEY tiles (36 iters), private 2-stage rings + named barriers,
// exp2-domain softmax.
// Smem words: QP union( Qstage[32][136]=4352 ; P: grp g at g*2304, [64][36] )
//           | rings: grp g at 4608 + g*8192, stage s at +s*4096
//             ( K [2 dpp][64 t][16] = 2048 | V [2 halves][64 d][16] = 2048 )
// ---------------------------------------------------------------------------
#define PST 36
#define OFF_R 4608
#define FLASH_WORDS (OFF_R + 2 * 8192)     // 20992
#define FLASH_BYTES (FLASH_WORDS * 4)      // 83968

#define FLASH_ISSUE_KV(s_, t0_) {                                              \
    unsigned* st_ = ringg + (s_) * 4096;                                       \
    _Pragma("unroll") for (int j_ = 0; j_ < 4; j_++) {                         \
        const int c_ = tidg * 16 + j_ * 4;                                     \
        cp16(st_ + c_, Kg + (size_t)(c_ >> 10) * 36864 +                       \
                            (size_t)(t0_) * 16 + (c_ & 1023));                 \
    }                                                                          \
    _Pragma("unroll") for (int j_ = 0; j_ < 4; j_++) {                         \
        const int c_ = tidg * 16 + j_ * 4;                                     \
        cp16(st_ + 2048 + c_, Vg + (size_t)((t0_) >> 5) * 1024 + c_);          \
    }                                                                          \
    cpcommit(); }

__global__ __launch_bounds__(256, 2) void flash_attn()
{
    extern __shared__ unsigned smw[];
    unsigned* QP = smw;   // Q staging, later per-group P

    const int tid  = threadIdx.x;
    const int warp = tid >> 5, lane = tid & 31;
    const int q = lane & 3, r = lane >> 2;
    const int g    = warp >> 2;
    const int tidg = tid & 127;
    const int rw   = warp * 16;
    const int rwl  = (warp & 3) * 16;
    unsigned* Pg   = QP + g * 2304;
    unsigned* ringg = smw + OFF_R + g * 8192;
    const int bh = blockIdx.y;
    const int s0 = blockIdx.x * 128;

    const unsigned* Qg = g_Q + (size_t)bh * 73728;
    const unsigned* Kg = g_K + (size_t)bh * 73728;
    const unsigned* Vg = g_V + (size_t)bh * 73728;

    // Q stage + first K/V tile of this group
#pragma unroll
    for (int j = 0; j < 4; j++) {
        const int c = tid * 16 + j * 4;
        const int dw = c >> 7, sc = c & 127;
        cp16(QP + dw * 136 + sc, Qg + (size_t)dw * 2304 + s0 + sc);
    }
    cpcommit();
    FLASH_ISSUE_KV(0, 0)
    cpwait<1>();
    __syncthreads();

    unsigned qa[4][4];
#pragma unroll
    for (int dp = 0; dp < 4; dp++) {
        qa[dp][0] = QP[(dp * 8 + q) * 136 + rw + r];
        qa[dp][1] = QP[(dp * 8 + q) * 136 + rw + r + 8];
        qa[dp][2] = QP[(dp * 8 + q + 4) * 136 + rw + r];
        qa[dp][3] = QP[(dp * 8 + q + 4) * 136 + rw + r + 8];
    }
    __syncthreads();   // all warps done with Qstage before P overwrites it

    float O[8][4];
#pragma unroll
    for (int i = 0; i < 8; i++)
#pragma unroll
        for (int j = 0; j < 4; j++) O[i][j] = 0.0f;

    float mA = -1e30f, mB = -1e30f, lA = 0.0f, lB = 0.0f;

    for (int it = 0; it < 36; it++) {
        cpwait<0>();
        asm volatile("bar.sync %0, 128;" :: "r"(g + 1) : "memory");
        if (it < 35) FLASH_ISSUE_KV((it + 1) & 1, (it + 1) * 64)
        unsigned* Ks = ringg + (it & 1) * 4096;
        unsigned* Vs = Ks + 2048;

        // S[16 warp rows][64 t] = Q . K
        float S[8][4];
#pragma unroll
        for (int tn = 0; tn < 8; tn++)
#pragma unroll
            for (int j = 0; j < 4; j++) S[tn][j] = 0.0f;

#pragma unroll
        for (int dpp = 0; dpp < 2; dpp++)
#pragma unroll
            for (int tn = 0; tn < 8; tn++) {
                const uint4 kb = *(const uint4*)&Ks[dpp * 1024 +
                                                    (tn * 8 + r) * 16 + q * 4];
                mma_f16(S[tn], qa[2 * dpp],     kb.x, kb.y);
                mma_f16(S[tn], qa[2 * dpp + 1], kb.z, kb.w);
            }

        // exp2-domain online softmax (rows rw+r and rw+r+8)
        float mxA = -1e30f, mxB = -1e30f;
#pragma unroll
        for (int tn = 0; tn < 8; tn++) {
            mxA = fmaxf(mxA, fmaxf(S[tn][0], S[tn][1]));
            mxB = fmaxf(mxB, fmaxf(S[tn][2], S[tn][3]));
        }
        mxA = fmaxf(mxA, __shfl_xor_sync(0xffffffffu, mxA, 1));
        mxA = fmaxf(mxA, __shfl_xor_sync(0xffffffffu, mxA, 2));
        mxB = fmaxf(mxB, __shfl_xor_sync(0xffffffffu, mxB, 1));
        mxB = fmaxf(mxB, __shfl_xor_sync(0xffffffffu, mxB, 2));

        const float mnA = fmaxf(mA, mxA), mnB = fmaxf(mB, mxB);
        const float cA = exp2f(mA - mnA), cB = exp2f(mB - mnB);
        float sA = 0.0f, sB = 0.0f;
#pragma unroll
        for (int tn = 0; tn < 8; tn++) {
            S[tn][0] = exp2f(S[tn][0] - mnA); sA += S[tn][0];
            S[tn][1] = exp2f(S[tn][1] - mnA); sA += S[tn][1];
            S[tn][2] = exp2f(S[tn][2] - mnB); sB += S[tn][2];
            S[tn][3] = exp2f(S[tn][3] - mnB); sB += S[tn][3];
        }
        sA += __shfl_xor_sync(0xffffffffu, sA, 1);
        sA += __shfl_xor_sync(0xffffffffu, sA, 2);
        sB += __shfl_xor_sync(0xffffffffu, sB, 1);
        sB += __shfl_xor_sync(0xffffffffu, sB, 2);

        lA = lA * cA + sA;  lB = lB * cB + sB;
        mA = mnA;           mB = mnB;
#pragma unroll
        for (int to = 0; to < 8; to++) {
            O[to][0] *= cA; O[to][1] *= cA;
            O[to][2] *= cB; O[to][3] *= cB;
        }

        // P as f16x2 t-pairs (t, t+8): slab s words s*8 + 2q, 2q+1
#pragma unroll
        for (int s = 0; s < 4; s++) {
            uint2 v;
            v.x = h2(S[2 * s][0], S[2 * s + 1][0]);
            v.y = h2(S[2 * s][1], S[2 * s + 1][1]);
            *(uint2*)&Pg[(rwl + r) * PST + s * 8 + 2 * q] = v;
            v.x = h2(S[2 * s][2], S[2 * s + 1][2]);
            v.y = h2(S[2 * s][3], S[2 * s + 1][3]);
            *(uint2*)&Pg[(rwl + r + 8) * PST + s * 8 + 2 * q] = v;
        }
        __syncwarp();

        // O += P . V : two 32-key halves, each with 2 k16 slabs
#pragma unroll
        for (int half = 0; half < 2; half++) {
            unsigned a0[4], a1[4];
            const int s0w = (half * 2) * 8, s1w = (half * 2 + 1) * 8;
            a0[0] = Pg[(rwl + r) * PST + s0w + q];
            a0[1] = Pg[(rwl + r + 8) * PST + s0w + q];
            a0[2] = Pg[(rwl + r) * PST + s0w + q + 4];
            a0[3] = Pg[(rwl + r + 8) * PST + s0w + q + 4];
            a1[0] = Pg[(rwl + r) * PST + s1w + q];
            a1[1] = Pg[(rwl + r + 8) * PST + s1w + q];
            a1[2] = Pg[(rwl + r) * PST + s1w + q + 4];
            a1[3] = Pg[(rwl + r + 8) * PST + s1w + q + 4];
#pragma unroll
            for (int to = 0; to < 8; to++) {
                const uint4 vb = *(const uint4*)&Vs[half * 1024 +
                                                    (to * 8 + r) * 16 + q * 4];
                mma_f16(O[to], a0, vb.x, vb.y);
                mma_f16(O[to], a1, vb.z, vb.w);
            }
        }
    }

    // normalize + store O as f16x2 channel-pairs for out_gemm
    const float iA = 1.0f / lA, iB = 1.0f / lB;
    const int sA0 = s0 + rw + r, sB0 = sA0 + 8;
    const int b_ = bh >> 3, h_ = bh & 7;
    const int pw0 = ((2 * q) & 3) * 2 + ((2 * q) >> 2);
    const int pw1 = ((2 * q + 1) & 3) * 2 + ((2 * q + 1) >> 2);
#pragma unroll
    for (int top = 0; top < 8; top += 2) {
        const size_t base = (size_t)(b_ * 32 + h_ * 4 + (top >> 1)) * 2304;
        g_O[(base + sA0) * 8 + pw0] = h2(O[top][0] * iA, O[top + 1][0] * iA);
        g_O[(base + sA0) * 8 + pw1] = h2(O[top][1] * iA, O[top + 1][1] * iA);
        g_O[(base + sB0) * 8 + pw0] = h2(O[top][2] * iB, O[top + 1][2] * iB);
        g_O[(base + sB0) * 8 + pw1] = h2(O[top][3] * iB, O[top + 1][3] * iB);
    }
}

// ---------------------------------------------------------------------------
extern "C" void kernel_launch(void* const* d_in, const int* in_sizes, int n_in,
                              void* d_out, int out_size)
{
    const float* x    = (const float*)d_in[0];
    const float* Wqkv = (const float*)d_in[1];
    const float* bqkv = (const float*)d_in[2];
    const float* Wout = (const float*)d_in[3];
    const float* bout = (const float*)d_in[4];
    float* out = (float*)d_out;

    cudaFuncSetAttribute(qkv_gemm,  cudaFuncAttributeMaxDynamicSharedMemorySize, PRJ_SMEM);
    cudaFuncSetAttribute(out_gemm,  cudaFuncAttributeMaxDynamicSharedMemorySize, PRJ_SMEM);
    cudaFuncSetAttribute(flash_attn, cudaFuncAttributeMaxDynamicSharedMemorySize, FLASH_BYTES);

    prep<<<1184, 256>>>(x, Wqkv, Wout);
    qkv_gemm<<<dim3(SEQ / 128, MQKV / 128, BATCH), 256, PRJ_SMEM>>>(bqkv);
    flash_attn<<<dim3(SEQ / 128, BATCH * NH), 256, FLASH_BYTES>>>();
    out_gemm<<<dim3(SEQ / 128, CDIM / 128, BATCH), 256, PRJ_SMEM>>>(bout, out);
}

// round 14
// speedup vs baseline: 1.1313x; 1.1313x over previous
#include <cuda_runtime.h>
#include <cuda_fp16.h>

// ---------------------------------------------------------------------------
// MultiHeadSelfAttention, fp16 mma.sync (m16n8k16, fp32 accum) + cp.async.
// R12 structure (best measured: 264.3us) + exp2-domain softmax (QSCALE
// pre-folds log2(e); flash uses bare MUFU.EX2 instead of FMUL+EX2).
//   prep      : x -> f16x2 pair-interleaved; Wqkv/Wout -> A-fragment order.
//   qkv_gemm  : BK=32, 4-stage one-barrier pipeline; Q scaled 0.125*log2(e).
//   flash_attn: two independent 4-warp groups, 32-key tiles, private 4-stage
//               rings + named barriers, exp2 softmax in registers.
//   out_gemm  : BK=32, 4-stage pipeline on f16x2 pair-interleaved O.
// ---------------------------------------------------------------------------

#define BATCH 4
#define CDIM  512
#define SEQ   2304
#define NH    8
#define HD    64
#define MQKV  1536
#define SCRH  (BATCH * CDIM * SEQ / 2)

#define QSCALE (0.125f * 1.4426950408889634f)   // d^-1/2 * log2(e)

__device__ __align__(16) unsigned g_Q[SCRH];   // [bh][dp*8+w][s]
__device__ __align__(16) unsigned g_K[SCRH];   // ((bh*2+dpp)*2304+t)*16 + p
__device__ __align__(16) unsigned g_V[SCRH];   // ((bh*72+tblk)*64+d)*16 + p
__device__ __align__(16) unsigned g_O[SCRH];   // ((b*32+ks)*2304+s)*8 + pw
__device__ __align__(16) unsigned g_Xt[SCRH];
__device__ __align__(16) unsigned g_Wq[MQKV * CDIM / 2];
__device__ __align__(16) unsigned g_Wo[CDIM * CDIM / 2];

__device__ __forceinline__ unsigned h2(float lo, float hi) {
    __half2 t = __floats2half2_rn(lo, hi);
    return *(unsigned*)&t;
}

__device__ __forceinline__ void mma_f16(float* c, const unsigned* a,
                                        unsigned b0, unsigned b1) {
    asm volatile(
        "mma.sync.aligned.m16n8k16.row.col.f32.f16.f16.f32 "
        "{%0,%1,%2,%3}, {%4,%5,%6,%7}, {%8,%9}, {%0,%1,%2,%3};"
        : "+f"(c[0]), "+f"(c[1]), "+f"(c[2]), "+f"(c[3])
        : "r"(a[0]), "r"(a[1]), "r"(a[2]), "r"(a[3]), "r"(b0), "r"(b1));
}

__device__ __forceinline__ void cp16(unsigned* dst, const unsigned* src) {
    unsigned da = (unsigned)__cvta_generic_to_shared(dst);
    asm volatile("cp.async.cg.shared.global [%0], [%1], 16;"
                 :: "r"(da), "l"(src));
}
__device__ __forceinline__ void cpcommit() {
    asm volatile("cp.async.commit_group;");
}
template <int N> __device__ __forceinline__ void cpwait() {
    asm volatile("cp.async.wait_group %0;" :: "n"(N));
}

// ---------------------------------------------------------------------------
__global__ void prep(const float* __restrict__ x,
                     const float* __restrict__ Wqkv,
                     const float* __restrict__ Wout)
{
    const int stride = gridDim.x * blockDim.x;
    const int i0 = blockIdx.x * blockDim.x + threadIdx.x;
    for (int o = i0; o < SCRH; o += stride) {
        const int pos = o & 7;
        const int idx = o >> 3;
        const int s = idx % 2304;
        const int slab = idx / 2304;
        const int w = (pos >> 1) + (pos & 1) * 4;
        const int b = slab >> 5;
        const int k = (slab & 31) * 16 + w;
        g_Xt[o] = h2(x[((size_t)(b * 512 + k)) * 2304 + s],
                     x[((size_t)(b * 512 + k + 8)) * 2304 + s]);
    }
    for (int o = i0; o < MQKV * CDIM / 2; o += stride) {
        const int j = o & 3, lane = (o >> 2) & 31, g = (o >> 7) & 7;
        const int ks = (o >> 10) & 31, mb = o >> 15;
        const int m = mb * 128 + g * 16 + (j & 1) * 8 + (lane >> 2);
        const int klo = ks * 16 + (lane & 3) + (j >> 1) * 4;
        g_Wq[o] = h2(Wqkv[m * CDIM + klo], Wqkv[m * CDIM + klo + 8]);
    }
    for (int o = i0; o < CDIM * CDIM / 2; o += stride) {
        const int j = o & 3, lane = (o >> 2) & 31, g = (o >> 7) & 7;
        const int ks = (o >> 10) & 31, mb = o >> 15;
        const int m = mb * 128 + g * 16 + (j & 1) * 8 + (lane >> 2);
        const int klo = ks * 16 + (lane & 3) + (j >> 1) * 4;
        g_Wo[o] = h2(Wout[m * CDIM + klo], Wout[m * CDIM + klo + 8]);
    }
}

// ---------------------------------------------------------------------------
// Projection mainloop: BK=32 (2 k16 steps), 4-stage one-barrier pipeline.
// ---------------------------------------------------------------------------
#define PRJ_STG  4096
#define PRJ_SMEM (4 * PRJ_STG * 4)

#define PRJ_ISSUE(s_, ks0_) {                                                  \
    unsigned* st_ = smp + (s_) * PRJ_STG;                                      \
    const unsigned* ws_ = Wg + (ks0_) * 1024;                                  \
    cp16(st_ + tid * 8,     ws_ + tid * 8);                                    \
    cp16(st_ + tid * 8 + 4, ws_ + tid * 8 + 4);                                \
    _Pragma("unroll") for (int j_ = 0; j_ < 2; j_++) {                         \
        const int c_ = tid * 2 + j_;                                           \
        const int sl_ = c_ >> 8, n_ = (c_ & 255) >> 1, h_ = (c_ & 1) * 4;      \
        cp16(st_ + 2048 + sl_ * 1024 + n_ * 8 + h_,                            \
             Xg + ((size_t)(ks0_) + sl_) * 18432 + n_ * 8 + h_);               \
    }                                                                          \
    cpcommit(); }

#define PRJ_MAINLOOP()                                                         \
    float acc[4][4][4];                                                        \
    _Pragma("unroll") for (int i = 0; i < 4; i++)                              \
    _Pragma("unroll") for (int j = 0; j < 4; j++)                              \
    _Pragma("unroll") for (int k = 0; k < 4; k++) acc[i][j][k] = 0.0f;         \
    PRJ_ISSUE(0, 0)                                                            \
    PRJ_ISSUE(1, 2)                                                            \
    PRJ_ISSUE(2, 4)                                                            \
    for (int it = 0; it < 16; it++) {                                          \
        if (it == 15) cpwait<0>();                                             \
        else if (it == 14) cpwait<1>();                                        \
        else cpwait<2>();                                                      \
        __syncthreads();                                                       \
        if (it < 13) PRJ_ISSUE((it + 3) & 3, (it + 3) * 2)                     \
        unsigned* Ws = smp + (it & 3) * PRJ_STG;                               \
        unsigned* Xs = Ws + 2048;                                              \
        _Pragma("unroll")                                                      \
        for (int ss = 0; ss < 2; ss++) {                                       \
            uint4 afr[4];                                                      \
            _Pragma("unroll") for (int tm = 0; tm < 4; tm++)                   \
                afr[tm] = *(const uint4*)&Ws[ss * 1024 +                       \
                                             ((wm >> 4) + tm) * 128 + lane * 4];\
            uint2 bfr[4];                                                      \
            _Pragma("unroll") for (int tn = 0; tn < 4; tn++)                   \
                bfr[tn] = *(const uint2*)&Xs[ss * 1024 +                       \
                                             (wn + tn * 8 + r) * 8 + q * 2];   \
            _Pragma("unroll") for (int tm = 0; tm < 4; tm++)                   \
            _Pragma("unroll") for (int tn = 0; tn < 4; tn++)                   \
                mma_f16(acc[tm][tn], (const unsigned*)&afr[tm],                \
                        bfr[tn].x, bfr[tn].y);                                 \
        }                                                                      \
    }

// ---------------------------------------------------------------------------
__global__ __launch_bounds__(256, 2) void qkv_gemm(const float* __restrict__ bias)
{
    extern __shared__ unsigned smp[];
    const int tid = threadIdx.x;
    const int b = blockIdx.z, m0 = blockIdx.y * 128, n0 = blockIdx.x * 128;
    const int lane = tid & 31, warp = tid >> 5;
    const int q = lane & 3, r = lane >> 2;
    const int wm = (warp >> 2) * 64, wn = (warp & 3) * 32;
    const unsigned* Wg = g_Wq + (size_t)(m0 >> 7) * 32768;
    const unsigned* Xg = g_Xt + (size_t)b * 589824 + (size_t)n0 * 8;

    PRJ_MAINLOOP()

    const int which = m0 >> 9;
    if (which == 0) {
#pragma unroll
        for (int tm = 0; tm < 4; tm++) {
            const int mA = m0 + wm + tm * 16 + r;
            const int loc = mA & 511, h = loc >> 6, dA = loc & 63;
            const int bh = b * NH + h, dp = dA >> 4;
            const float bvA = bias[mA], bvB = bias[mA + 8];
            unsigned* row = g_Q + (size_t)(bh * 32 + dp * 8 + r) * 2304;
#pragma unroll
            for (int tn = 0; tn < 4; tn++) {
                const int n = n0 + wn + tn * 8 + 2 * q;
                uint2 v;
                v.x = h2((acc[tm][tn][0] + bvA) * QSCALE,
                         (acc[tm][tn][2] + bvB) * QSCALE);
                v.y = h2((acc[tm][tn][1] + bvA) * QSCALE,
                         (acc[tm][tn][3] + bvB) * QSCALE);
                *(uint2*)(row + n) = v;
            }
        }
    } else if (which == 1) {
#pragma unroll
        for (int tm = 0; tm < 4; tm++) {
            const int mA = m0 + wm + tm * 16 + r;
            const int loc = mA & 511, h = loc >> 6, dA = loc & 63;
            const int bh = b * NH + h, dp = dA >> 4;
            const int p0 = (r & 3) * 4 + (r >> 2) + 2 * (dp & 1);
            const float bvA = bias[mA], bvB = bias[mA + 8];
            const size_t base = (size_t)(bh * 2 + (dp >> 1)) * 36864 + p0;
#pragma unroll
            for (int tn = 0; tn < 4; tn++) {
                const int n = n0 + wn + tn * 8 + 2 * q;
                g_K[base + (size_t)n * 16]       = h2(acc[tm][tn][0] + bvA,
                                                      acc[tm][tn][2] + bvB);
                g_K[base + (size_t)(n + 1) * 16] = h2(acc[tm][tn][1] + bvA,
                                                      acc[tm][tn][3] + bvB);
            }
        }
    } else {
#pragma unroll
        for (int tm = 0; tm < 4; tm++) {
            const int mA = m0 + wm + tm * 16 + r;
            const int loc = mA & 511, h = loc >> 6, dA = loc & 63;
            const int bh = b * NH + h;
            const float bvA = bias[mA], bvB = bias[mA + 8];
#pragma unroll
            for (int tnp = 0; tnp < 2; tnp++) {
                const int tn = tnp * 2;
                const int t0 = n0 + wn + tn * 8 + 2 * q;
                const int sub = (t0 >> 4) & 1;
                const int p0 = ((2 * q) & 3) * 4 + ((2 * q) >> 2) + 2 * sub;
                const int p1 = ((2 * q + 1) & 3) * 4 + ((2 * q + 1) >> 2) + 2 * sub;
                const size_t blk = (size_t)(bh * 72 + (t0 >> 5)) * 1024;
                g_V[blk + dA * 16 + p0] = h2(acc[tm][tn][0] + bvA,
                                             acc[tm][tn + 1][0] + bvA);
                g_V[blk + dA * 16 + p1] = h2(acc[tm][tn][1] + bvA,
                                             acc[tm][tn + 1][1] + bvA);
                g_V[blk + (dA + 8) * 16 + p0] = h2(acc[tm][tn][2] + bvB,
                                                   acc[tm][tn + 1][2] + bvB);
                g_V[blk + (dA + 8) * 16 + p1] = h2(acc[tm][tn][3] + bvB,
                                                   acc[tm][tn + 1][3] + bvB);
            }
        }
    }
}

// ---------------------------------------------------------------------------
__global__ __launch_bounds__(256, 2) void out_gemm(const float* __restrict__ bias,
                                                   float* __restrict__ Y)
{
    extern __shared__ unsigned smp[];
    const int tid = threadIdx.x;
    const int b = blockIdx.z, m0 = blockIdx.y * 128, n0 = blockIdx.x * 128;
    const int lane = tid & 31, warp = tid >> 5;
    const int q = lane & 3, r = lane >> 2;
    const int wm = (warp >> 2) * 64, wn = (warp & 3) * 32;
    const unsigned* Wg = g_Wo + (size_t)(m0 >> 7) * 32768;
    const unsigned* Xg = g_O + (size_t)b * 589824 + (size_t)n0 * 8;

    PRJ_MAINLOOP()

#pragma unroll
    for (int tm = 0; tm < 4; tm++) {
        const int mA = m0 + wm + tm * 16 + r;
        const float bvA = bias[mA], bvB = bias[mA + 8];
        float* rowA = Y + ((size_t)b * CDIM + mA) * SEQ;
        float* rowB = Y + ((size_t)b * CDIM + mA + 8) * SEQ;
#pragma unroll
        for (int tn = 0; tn < 4; tn++) {
            const int n = n0 + wn + tn * 8 + 2 * q;
            *(float2*)(rowA + n) = make_float2(acc[tm][tn][0] + bvA,
                                               acc[tm][tn][1] + bvA);
            *(float2*)(rowB + n) = make_float2(acc[tm][tn][2] + bvB,
                                               acc[tm][tn][3] + bvB);
        }
    }
}

// ---------------------------------------------------------------------------
// flash_attn (R12 structure): grid (18, 32), 256 thr, 2 CTAs/SM. Two
// independent 4-warp groups, 32-key tiles, 4-stage rings (wait_group 2),
// named barriers, exp2-domain softmax.
// ---------------------------------------------------------------------------
#define PST 20
#define OFF_R 4352
#define FLASH_WORDS (OFF_R + 2 * 8192)     // 20736
#define FLASH_BYTES (FLASH_WORDS * 4)      // 82944

#define FLASH_ISSUE_KV(s_, t0_) {                                              \
    unsigned* st_ = ringg + (s_) * 2048;                                       \
    _Pragma("unroll") for (int j_ = 0; j_ < 2; j_++) {                         \
        const int c_ = tidg * 8 + j_ * 4;                                      \
        cp16(st_ + c_, Kg + (size_t)(c_ >> 9) * 36864 +                        \
                            (size_t)(t0_) * 16 + (c_ & 511));                  \
    }                                                                          \
    _Pragma("unroll") for (int j_ = 0; j_ < 2; j_++) {                         \
        const int c_ = tidg * 8 + j_ * 4;                                      \
        cp16(st_ + 1024 + c_, Vg + (size_t)((t0_) >> 5) * 1024 + c_);          \
    }                                                                          \
    cpcommit(); }

__global__ __launch_bounds__(256, 2) void flash_attn()
{
    extern __shared__ unsigned smw[];
    unsigned* QP = smw;   // Q staging, later per-group P

    const int tid  = threadIdx.x;
    const int warp = tid >> 5, lane = tid & 31;
    const int q = lane & 3, r = lane >> 2;
    const int g    = warp >> 2;
    const int tidg = tid & 127;
    const int rw   = warp * 16;
    const int rwl  = (warp & 3) * 16;
    unsigned* Pg   = QP + g * 1280;
    unsigned* ringg = smw + OFF_R + g * 8192;
    const int bh = blockIdx.y;
    const int s0 = blockIdx.x * 128;

    const unsigned* Qg = g_Q + (size_t)bh * 73728;
    const unsigned* Kg = g_K + (size_t)bh * 73728;
    const unsigned* Vg = g_V + (size_t)bh * 73728;

    // Q stage + first three K/V tiles of this group
#pragma unroll
    for (int j = 0; j < 4; j++) {
        const int c = tid * 16 + j * 4;
        const int dw = c >> 7, sc = c & 127;
        cp16(QP + dw * 136 + sc, Qg + (size_t)dw * 2304 + s0 + sc);
    }
    cpcommit();
    FLASH_ISSUE_KV(0, 0)
    FLASH_ISSUE_KV(1, 32)
    FLASH_ISSUE_KV(2, 64)
    cpwait<3>();
    __syncthreads();

    unsigned qa[4][4];
#pragma unroll
    for (int dp = 0; dp < 4; dp++) {
        qa[dp][0] = QP[(dp * 8 + q) * 136 + rw + r];
        qa[dp][1] = QP[(dp * 8 + q) * 136 + rw + r + 8];
        qa[dp][2] = QP[(dp * 8 + q + 4) * 136 + rw + r];
        qa[dp][3] = QP[(dp * 8 + q + 4) * 136 + rw + r + 8];
    }
    __syncthreads();   // all warps done with Qstage before P overwrites it

    float O[8][4];
#pragma unroll
    for (int i = 0; i < 8; i++)
#pragma unroll
        for (int j = 0; j < 4; j++) O[i][j] = 0.0f;

    float mA = -1e30f, mB = -1e30f, lA = 0.0f, lB = 0.0f;

    for (int it = 0; it < 72; it++) {
        if (it <= 69) cpwait<2>();
        else if (it == 70) cpwait<1>();
        else cpwait<0>();
        asm volatile("bar.sync %0, 128;" :: "r"(g + 1) : "memory");
        if (it < 69) FLASH_ISSUE_KV((it + 3) & 3, (it + 3) * 32)
        unsigned* Ks = ringg + (it & 3) * 2048;
        unsigned* Vs = Ks + 1024;

        // S[16 warp rows][32 t] = Q . K
        float S[4][4];
#pragma unroll
        for (int tn = 0; tn < 4; tn++)
#pragma unroll
            for (int j = 0; j < 4; j++) S[tn][j] = 0.0f;

#pragma unroll
        for (int dpp = 0; dpp < 2; dpp++)
#pragma unroll
            for (int tn = 0; tn < 4; tn++) {
                const uint4 kb = *(const uint4*)&Ks[dpp * 512 +
                                                    (tn * 8 + r) * 16 + q * 4];
                mma_f16(S[tn], qa[2 * dpp],     kb.x, kb.y);
                mma_f16(S[tn], qa[2 * dpp + 1], kb.z, kb.w);
            }

        // exp2-domain online softmax (rows rw+r and rw+r+8)
        float mxA = -1e30f, mxB = -1e30f;
#pragma unroll
        for (int tn = 0; tn < 4; tn++) {
            mxA = fmaxf(mxA, fmaxf(S[tn][0], S[tn][1]));
            mxB = fmaxf(mxB, fmaxf(S[tn][2], S[tn][3]));
        }
        mxA = fmaxf(mxA, __shfl_xor_sync(0xffffffffu, mxA, 1));
        mxA = fmaxf(mxA, __shfl_xor_sync(0xffffffffu, mxA, 2));
        mxB = fmaxf(mxB, __shfl_xor_sync(0xffffffffu, mxB, 1));
        mxB = fmaxf(mxB, __shfl_xor_sync(0xffffffffu, mxB, 2));

        const float mnA = fmaxf(mA, mxA), mnB = fmaxf(mB, mxB);
        const float cA = exp2f(mA - mnA), cB = exp2f(mB - mnB);
        float sA = 0.0f, sB = 0.0f;
#pragma unroll
        for (int tn = 0; tn < 4; tn++) {
            S[tn][0] = exp2f(S[tn][0] - mnA); sA += S[tn][0];
            S[tn][1] = exp2f(S[tn][1] - mnA); sA += S[tn][1];
            S[tn][2] = exp2f(S[tn][2] - mnB); sB += S[tn][2];
            S[tn][3] = exp2f(S[tn][3] - mnB); sB += S[tn][3];
        }
        sA += __shfl_xor_sync(0xffffffffu, sA, 1);
        sA += __shfl_xor_sync(0xffffffffu, sA, 2);
        sB += __shfl_xor_sync(0xffffffffu, sB, 1);
        sB += __shfl_xor_sync(0xffffffffu, sB, 2);

        lA = lA * cA + sA;  lB = lB * cB + sB;
        mA = mnA;           mB = mnB;
#pragma unroll
        for (int to = 0; to < 8; to++) {
            O[to][0] *= cA; O[to][1] *= cA;
            O[to][2] *= cB; O[to][3] *= cB;
        }

        // P as f16x2 t-pairs (t, t+8)
        {
            uint2 v;
            v.x = h2(S[0][0], S[1][0]); v.y = h2(S[0][1], S[1][1]);
            *(uint2*)&Pg[(rwl + r) * PST + 2 * q] = v;
            v.x = h2(S[2][0], S[3][0]); v.y = h2(S[2][1], S[3][1]);
            *(uint2*)&Pg[(rwl + r) * PST + 8 + 2 * q] = v;
            v.x = h2(S[0][2], S[1][2]); v.y = h2(S[0][3], S[1][3]);
            *(uint2*)&Pg[(rwl + r + 8) * PST + 2 * q] = v;
            v.x = h2(S[2][2], S[3][2]); v.y = h2(S[2][3], S[3][3]);
            *(uint2*)&Pg[(rwl + r + 8) * PST + 8 + 2 * q] = v;
        }
        __syncwarp();

        // O += P . V
#pragma unroll
        for (int slab = 0; slab < 2; slab++) {
            unsigned a[4];
            a[0] = Pg[(rwl + r) * PST + slab * 8 + q];
            a[1] = Pg[(rwl + r + 8) * PST + slab * 8 + q];
            a[2] = Pg[(rwl + r) * PST + slab * 8 + q + 4];
            a[3] = Pg[(rwl + r + 8) * PST + slab * 8 + q + 4];
            if (slab == 0) {
#pragma unroll
                for (int to = 0; to < 8; to++) {
                    const uint4 vb = *(const uint4*)&Vs[(to * 8 + r) * 16 + q * 4];
                    mma_f16(O[to], a, vb.x, vb.y);
                }
            } else {
#pragma unroll
                for (int to = 0; to < 8; to++) {
                    const uint4 vb = *(const uint4*)&Vs[(to * 8 + r) * 16 + q * 4];
                    mma_f16(O[to], a, vb.z, vb.w);
                }
            }
        }
    }

    // normalize + store O as f16x2 channel-pairs for out_gemm
    const float iA = 1.0f / lA, iB = 1.0f / lB;
    const int sA0 = s0 + rw + r, sB0 = sA0 + 8;
    const int b_ = bh >> 3, h_ = bh & 7;
    const int pw0 = ((2 * q) & 3) * 2 + ((2 * q) >> 2);
    const int pw1 = ((2 * q + 1) & 3) * 2 + ((2 * q + 1) >> 2);
#pragma unroll
    for (int top = 0; top < 8; top += 2) {
        const size_t base = (size_t)(b_ * 32 + h_ * 4 + (top >> 1)) * 2304;
        g_O[(base + sA0) * 8 + pw0] = h2(O[top][0] * iA, O[top + 1][0] * iA);
        g_O[(base + sA0) * 8 + pw1] = h2(O[top][1] * iA, O[top + 1][1] * iA);
        g_O[(base + sB0) * 8 + pw0] = h2(O[top][2] * iB, O[top + 1][2] * iB);
        g_O[(base + sB0) * 8 + pw1] = h2(O[top][3] * iB, O[top + 1][3] * iB);
    }
}

// ---------------------------------------------------------------------------
extern "C" void kernel_launch(void* const* d_in, const int* in_sizes, int n_in,
                              void* d_out, int out_size)
{
    const float* x    = (const float*)d_in[0];
    const float* Wqkv = (const float*)d_in[1];
    const float* bqkv = (const float*)d_in[2];
    const float* Wout = (const float*)d_in[3];
    const float* bout = (const float*)d_in[4];
    float* out = (float*)d_out;

    cudaFuncSetAttribute(qkv_gemm,  cudaFuncAttributeMaxDynamicSharedMemorySize, PRJ_SMEM);
    cudaFuncSetAttribute(out_gemm,  cudaFuncAttributeMaxDynamicSharedMemorySize, PRJ_SMEM);
    cudaFuncSetAttribute(flash_attn, cudaFuncAttributeMaxDynamicSharedMemorySize, FLASH_BYTES);

    prep<<<1184, 256>>>(x, Wqkv, Wout);
    qkv_gemm<<<dim3(SEQ / 128, MQKV / 128, BATCH), 256, PRJ_SMEM>>>(bqkv);
    flash_attn<<<dim3(SEQ / 128, BATCH * NH), 256, FLASH_BYTES>>>();
    out_gemm<<<dim3(SEQ / 128, CDIM / 128, BATCH), 256, PRJ_SMEM>>>(bout, out);
}